// round 2
// baseline (speedup 1.0000x reference)
#include <cuda_runtime.h>
#include <math.h>

// ---------------- problem constants ----------------
#define BB 2
#define SS 2048
#define DD 768
#define HH 12
#define DEPTH 64
#define DFF 3072
#define NROWS (BB*SS)          // 4096
#define LN_EPS 1e-5f

// ---------------- scratch (device globals: no allocs allowed) ----------------
__device__ float g_qkv[NROWS * 3 * DD];   // 4096 x 2304
__device__ float g_ctx[NROWS * DD];       // 4096 x 768
__device__ float g_tmp[NROWS * DD];       // attn_out / ffn_out
__device__ float g_h  [NROWS * DD];       // LN1 output
__device__ float g_ff [NROWS * DFF];      // 4096 x 3072

// ======================================================================
// SGEMM: C[M,N] = A[M,K] @ B[K,N] (+bias) (+relu)
// 128x128x8 tile, 256 threads, 8x8 per thread. Requires M%128==0, N%128==0, K%8==0.
// ======================================================================
template<bool BIAS, bool RELU>
__global__ __launch_bounds__(256, 2)
void sgemm128(const float* __restrict__ A, const float* __restrict__ Bm,
              const float* __restrict__ bias, float* __restrict__ C,
              int M, int N, int K)
{
    __shared__ float As[8][128];
    __shared__ float Bs[8][128];

    const int t    = threadIdx.x;
    const int brow = blockIdx.y * 128;
    const int bcol = blockIdx.x * 128;
    const int ty   = t >> 4;       // 0..15
    const int tx   = t & 15;       // 0..15

    const int arow = t >> 1;           // 0..127
    const int acol = (t & 1) * 4;      // 0 or 4
    const int brl  = t >> 5;           // 0..7
    const int bcl  = (t & 31) * 4;     // 0..124

    const float* Ap = A  + (size_t)(brow + arow) * K + acol;
    const float* Bp = Bm + (size_t)brl * N + bcol + bcl;

    float acc[8][8];
    #pragma unroll
    for (int i = 0; i < 8; i++)
        #pragma unroll
        for (int j = 0; j < 8; j++)
            acc[i][j] = 0.f;

    for (int k0 = 0; k0 < K; k0 += 8) {
        float4 av = *(const float4*)(Ap + k0);
        float4 bv = *(const float4*)(Bp + (size_t)k0 * N);
        As[acol + 0][arow] = av.x;
        As[acol + 1][arow] = av.y;
        As[acol + 2][arow] = av.z;
        As[acol + 3][arow] = av.w;
        *(float4*)&Bs[brl][bcl] = bv;
        __syncthreads();

        #pragma unroll
        for (int k = 0; k < 8; k++) {
            float ra[8], rb[8];
            *(float4*)(ra)     = *(const float4*)&As[k][ty * 8];
            *(float4*)(ra + 4) = *(const float4*)&As[k][ty * 8 + 4];
            *(float4*)(rb)     = *(const float4*)&Bs[k][tx * 8];
            *(float4*)(rb + 4) = *(const float4*)&Bs[k][tx * 8 + 4];
            #pragma unroll
            for (int i = 0; i < 8; i++)
                #pragma unroll
                for (int j = 0; j < 8; j++)
                    acc[i][j] = fmaf(ra[i], rb[j], acc[i][j]);
        }
        __syncthreads();
    }

    // epilogue
    #pragma unroll
    for (int i = 0; i < 8; i++) {
        const int row = brow + ty * 8 + i;
        #pragma unroll
        for (int j = 0; j < 8; j += 4) {
            const int col = bcol + tx * 8 + j;
            float4 v;
            v.x = acc[i][j];   v.y = acc[i][j+1];
            v.z = acc[i][j+2]; v.w = acc[i][j+3];
            if (BIAS) {
                v.x += bias[col];   v.y += bias[col+1];
                v.z += bias[col+2]; v.w += bias[col+3];
            }
            if (RELU) {
                v.x = fmaxf(v.x, 0.f); v.y = fmaxf(v.y, 0.f);
                v.z = fmaxf(v.z, 0.f); v.w = fmaxf(v.w, 0.f);
            }
            *(float4*)&C[(size_t)row * N + col] = v;
        }
    }
}

// ======================================================================
// Causal flash attention, fp32, DEPTH=64. 64-query x 64-key tiles.
// grid = (S/64, B*H), block = 256. Dynamic smem = 67584 B.
// qkv layout: row (b*S+s) x 2304; q at col h*64, k at 768+h*64, v at 1536+h*64.
// Output ctx: (b*S+s) x 768, head-concat layout.
// ======================================================================
#define ATTN_SMEM ((64*64*2 + 64*68*2) * 4)

__global__ __launch_bounds__(256)
void attn_kernel(const float* __restrict__ qkv, float* __restrict__ ctx)
{
    extern __shared__ float sm[];
    float* Qs = sm;               // [d][q]  64x64 (depth-major)
    float* Ks = Qs + 64 * 64;     // [d][k]  64x64
    float* Vs = Ks + 64 * 64;     // [k][d]  pitch 68
    float* Ps = Vs + 64 * 68;     // [k][q]  pitch 68

    const int qt = (gridDim.x - 1) - blockIdx.x;   // heavy tiles first
    const int bh = blockIdx.y;
    const int b  = bh / HH;
    const int h  = bh % HH;

    const float* base = qkv + (size_t)b * SS * (3 * DD);

    const int t  = threadIdx.x;
    const int ty = t >> 4, tx = t & 15;
    const int r0 = ty * 4, c0 = tx * 4;

    const int lr = t & 63;         // row within 64-tile
    const int ld = (t >> 6) * 16;  // depth chunk start

    // load Q tile (pre-scaled by 1/sqrt(64))
    {
        const float* qp = base + (size_t)(qt * 64 + lr) * (3 * DD) + h * 64 + ld;
        #pragma unroll
        for (int i = 0; i < 16; i += 4) {
            float4 v4 = *(const float4*)(qp + i);
            Qs[(ld + i + 0) * 64 + lr] = v4.x * 0.125f;
            Qs[(ld + i + 1) * 64 + lr] = v4.y * 0.125f;
            Qs[(ld + i + 2) * 64 + lr] = v4.z * 0.125f;
            Qs[(ld + i + 3) * 64 + lr] = v4.w * 0.125f;
        }
    }

    float O[4][4];
    float m[4], l[4];
    #pragma unroll
    for (int i = 0; i < 4; i++) {
        m[i] = -1e30f; l[i] = 0.f;
        #pragma unroll
        for (int j = 0; j < 4; j++) O[i][j] = 0.f;
    }

    for (int kt = 0; kt <= qt; kt++) {
        __syncthreads();   // protect Ks/Vs (+ first-iter Qs) from prior reads
        {
            const float* kp = base + (size_t)(kt * 64 + lr) * (3 * DD) + DD + h * 64 + ld;
            const float* vp = kp + DD;
            #pragma unroll
            for (int i = 0; i < 16; i += 4) {
                float4 kv = *(const float4*)(kp + i);
                Ks[(ld + i + 0) * 64 + lr] = kv.x;
                Ks[(ld + i + 1) * 64 + lr] = kv.y;
                Ks[(ld + i + 2) * 64 + lr] = kv.z;
                Ks[(ld + i + 3) * 64 + lr] = kv.w;
                float4 vv = *(const float4*)(vp + i);
                *(float4*)&Vs[lr * 68 + ld + i] = vv;
            }
        }
        __syncthreads();

        // scores: s = (Q/8) @ K^T  (64x64x64)
        float s[4][4];
        #pragma unroll
        for (int i = 0; i < 4; i++)
            #pragma unroll
            for (int j = 0; j < 4; j++) s[i][j] = 0.f;

        #pragma unroll 4
        for (int d = 0; d < 64; d++) {
            float4 a  = *(const float4*)&Qs[d * 64 + r0];
            float4 bq = *(const float4*)&Ks[d * 64 + c0];
            float ra[4] = {a.x, a.y, a.z, a.w};
            float rb[4] = {bq.x, bq.y, bq.z, bq.w};
            #pragma unroll
            for (int i = 0; i < 4; i++)
                #pragma unroll
                for (int j = 0; j < 4; j++)
                    s[i][j] = fmaf(ra[i], rb[j], s[i][j]);
        }

        // causal mask on diagonal tile
        if (kt == qt) {
            #pragma unroll
            for (int i = 0; i < 4; i++)
                #pragma unroll
                for (int j = 0; j < 4; j++)
                    if (c0 + j > r0 + i) s[i][j] = -1e30f;
        }

        // online softmax
        #pragma unroll
        for (int i = 0; i < 4; i++) {
            float rmax = fmaxf(fmaxf(s[i][0], s[i][1]), fmaxf(s[i][2], s[i][3]));
            #pragma unroll
            for (int o = 8; o >= 1; o >>= 1)
                rmax = fmaxf(rmax, __shfl_xor_sync(0xffffffffu, rmax, o));
            float mn = fmaxf(m[i], rmax);
            float scale = __expf(m[i] - mn);
            float rsum = 0.f;
            #pragma unroll
            for (int j = 0; j < 4; j++) {
                float p = __expf(s[i][j] - mn);
                s[i][j] = p;
                rsum += p;
            }
            #pragma unroll
            for (int o = 8; o >= 1; o >>= 1)
                rsum += __shfl_xor_sync(0xffffffffu, rsum, o);
            l[i] = l[i] * scale + rsum;
            m[i] = mn;
            #pragma unroll
            for (int j = 0; j < 4; j++) O[i][j] *= scale;
        }

        // write P transposed: Ps[key][query]
        #pragma unroll
        for (int j = 0; j < 4; j++)
            #pragma unroll
            for (int i = 0; i < 4; i++)
                Ps[(c0 + j) * 68 + (r0 + i)] = s[i][j];
        __syncthreads();

        // O += P @ V   (64x64x64)
        #pragma unroll 4
        for (int k = 0; k < 64; k++) {
            float4 pv = *(const float4*)&Ps[k * 68 + r0];
            float4 vv = *(const float4*)&Vs[k * 68 + c0];
            float rp[4] = {pv.x, pv.y, pv.z, pv.w};
            float rv[4] = {vv.x, vv.y, vv.z, vv.w};
            #pragma unroll
            for (int i = 0; i < 4; i++)
                #pragma unroll
                for (int j = 0; j < 4; j++)
                    O[i][j] = fmaf(rp[i], rv[j], O[i][j]);
        }
    }

    // write ctx (head-concat): ctx[(b*S+q)*768 + h*64 + d]
    #pragma unroll
    for (int i = 0; i < 4; i++) {
        const float inv = 1.f / l[i];
        const size_t row = (size_t)(b * SS + qt * 64 + r0 + i) * DD + h * 64 + c0;
        float4 v;
        v.x = O[i][0] * inv; v.y = O[i][1] * inv;
        v.z = O[i][2] * inv; v.w = O[i][3] * inv;
        *(float4*)&ctx[row] = v;
    }
}

// ======================================================================
// Fused residual + LayerNorm: out = gain * norm(a+b) + beta, row length 768.
// grid = NROWS, block = 256 (3 elements/thread).
// ======================================================================
__global__ __launch_bounds__(256)
void ln_residual(const float* __restrict__ a, const float* __restrict__ b,
                 const float* __restrict__ gain, const float* __restrict__ beta,
                 float* __restrict__ out)
{
    const int row = blockIdx.x;
    const float* pa = a + (size_t)row * DD;
    const float* pb = b + (size_t)row * DD;

    float v[3];
    float s = 0.f, s2 = 0.f;
    #pragma unroll
    for (int i = 0; i < 3; i++) {
        const int c = threadIdx.x + i * 256;
        float x = pa[c] + pb[c];
        v[i] = x;
        s  += x;
        s2 = fmaf(x, x, s2);
    }

    __shared__ float sm1[8], sm2[8];
    #pragma unroll
    for (int o = 16; o >= 1; o >>= 1) {
        s  += __shfl_xor_sync(0xffffffffu, s,  o);
        s2 += __shfl_xor_sync(0xffffffffu, s2, o);
    }
    const int w = threadIdx.x >> 5, lane = threadIdx.x & 31;
    if (lane == 0) { sm1[w] = s; sm2[w] = s2; }
    __syncthreads();
    if (w == 0) {
        s  = (lane < 8) ? sm1[lane] : 0.f;
        s2 = (lane < 8) ? sm2[lane] : 0.f;
        #pragma unroll
        for (int o = 4; o >= 1; o >>= 1) {
            s  += __shfl_xor_sync(0xffffffffu, s,  o);
            s2 += __shfl_xor_sync(0xffffffffu, s2, o);
        }
        if (lane == 0) { sm1[0] = s; sm2[0] = s2; }
    }
    __syncthreads();

    const float mean = sm1[0] * (1.f / DD);
    const float var  = sm2[0] * (1.f / DD) - mean * mean;
    const float inv  = rsqrtf(var + LN_EPS);

    #pragma unroll
    for (int i = 0; i < 3; i++) {
        const int c = threadIdx.x + i * 256;
        out[(size_t)row * DD + c] = gain[c] * (v[i] - mean) * inv + beta[c];
    }
}

// ======================================================================
// launch
// ======================================================================
extern "C" void kernel_launch(void* const* d_in, const int* in_sizes, int n_in,
                              void* d_out, int out_size)
{
    const float* x    = (const float*)d_in[0];
    const float* Wqkv = (const float*)d_in[1];
    const float* Wout = (const float*)d_in[2];
    const float* bout = (const float*)d_in[3];
    const float* W1   = (const float*)d_in[4];
    const float* b1   = (const float*)d_in[5];
    const float* W2   = (const float*)d_in[6];
    const float* b2   = (const float*)d_in[7];
    const float* g1   = (const float*)d_in[8];
    const float* be1  = (const float*)d_in[9];
    const float* g2   = (const float*)d_in[10];
    const float* be2  = (const float*)d_in[11];
    float* out = (float*)d_out;

    float *qkv, *ctx, *tmp, *h, *ff;
    cudaGetSymbolAddress((void**)&qkv, g_qkv);
    cudaGetSymbolAddress((void**)&ctx, g_ctx);
    cudaGetSymbolAddress((void**)&tmp, g_tmp);
    cudaGetSymbolAddress((void**)&h,   g_h);
    cudaGetSymbolAddress((void**)&ff,  g_ff);

    cudaFuncSetAttribute(attn_kernel,
                         cudaFuncAttributeMaxDynamicSharedMemorySize, ATTN_SMEM);

    dim3 blk(256);

    // 1) QKV projection: (4096x768) @ (768x2304)
    sgemm128<false, false><<<dim3((3 * DD) / 128, NROWS / 128), blk>>>(
        x, Wqkv, nullptr, qkv, NROWS, 3 * DD, DD);

    // 2) causal attention -> ctx
    attn_kernel<<<dim3(SS / 64, BB * HH), blk, ATTN_SMEM>>>(qkv, ctx);

    // 3) output projection + bias
    sgemm128<true, false><<<dim3(DD / 128, NROWS / 128), blk>>>(
        ctx, Wout, bout, tmp, NROWS, DD, DD);

    // 4) LN1(x + attn_out) -> h
    ln_residual<<<NROWS, 256>>>(x, tmp, g1, be1, h);

    // 5) FFN up + bias + relu
    sgemm128<true, true><<<dim3(DFF / 128, NROWS / 128), blk>>>(
        h, W1, b1, ff, NROWS, DFF, DD);

    // 6) FFN down + bias
    sgemm128<true, false><<<dim3(DD / 128, NROWS / 128), blk>>>(
        ff, W2, b2, tmp, NROWS, DD, DFF);

    // 7) LN2(h + ff) -> out
    ln_residual<<<NROWS, 256>>>(h, tmp, g2, be2, out);
}